// round 3
// baseline (speedup 1.0000x reference)
#include <cuda_runtime.h>
#include <math.h>

#define BB 4096
#define SS 200
#define DD 64
#define VV 100000

// Static device scratch (allocation-free per harness rules)
__device__ float g_proj[VV * 8];   // [v][k] = emb_table[v] . att_w[k] + att_b[k], padded to 8
__device__ float g_loss[BB];       // per-batch loss, reduced deterministically

__device__ __forceinline__ float fast_tanh(float x) {
    float ax = fabsf(x);
    float t  = __expf(-2.0f * ax);
    float r  = __fdividef(1.0f - t, 1.0f + t);
    return copysignf(r, x);
}

// ---------------------------------------------------------------------------
// Kernel 1: precompute proj[v][k] = dot(emb_table[v], att_w[k]) + att_b[k]
// ---------------------------------------------------------------------------
__global__ void proj_kernel(const float* __restrict__ emb,
                            const float* __restrict__ aw,
                            const float* __restrict__ ab) {
    __shared__ float sw[320];
    __shared__ float sb[5];
    int tid = threadIdx.x;
    if (tid < 320) sw[tid] = aw[tid];
    if (tid < 5)   sb[tid] = ab[tid];
    __syncthreads();

    int v = blockIdx.x * blockDim.x + tid;
    if (v >= VV) return;

    const float4* row = (const float4*)(emb + (size_t)v * DD);
    float p[5] = {sb[0], sb[1], sb[2], sb[3], sb[4]};
#pragma unroll
    for (int i = 0; i < 16; i++) {
        float4 e = row[i];
        float ev[4] = {e.x, e.y, e.z, e.w};
#pragma unroll
        for (int c = 0; c < 4; c++) {
            int d = 4 * i + c;
#pragma unroll
            for (int k = 0; k < 5; k++)
                p[k] = fmaf(ev[c], sw[k * 64 + d], p[k]);
        }
    }
    float4* o = (float4*)(g_proj + (size_t)v * 8);
    o[0] = make_float4(p[0], p[1], p[2], p[3]);
    o[1] = make_float4(p[4], 0.0f, 0.0f, 0.0f);
}

// ---------------------------------------------------------------------------
// Kernel 2: main fused kernel. One warp per batch element b.
//   Phase A: lane r handles row s=cs+r: gather proj, g = exp(tanh(.)).
//   Phase B: 4 rows per sub-iter; lane group of 8 covers 64 dims (8 per lane).
// ---------------------------------------------------------------------------
__global__ void __launch_bounds__(128)
main_kernel(const int*   __restrict__ x,
            const float* __restrict__ y,
            const float* __restrict__ emb,
            const float* __restrict__ W0, const float* __restrict__ W1,
            const float* __restrict__ W2, const float* __restrict__ W3,
            const float* __restrict__ W4,
            float* __restrict__ out) {
    const int lane = threadIdx.x & 31;
    const int warp = threadIdx.x >> 5;
    const int b    = blockIdx.x * 4 + warp;
    const int sub  = lane & 7;   // dim octet (phase B)
    const int grp  = lane >> 3;  // row within 4-row group (phase B)

    float acc[5][8];
#pragma unroll
    for (int k = 0; k < 5; k++)
#pragma unroll
        for (int j = 0; j < 8; j++) acc[k][j] = 0.0f;
    float lsum[5] = {0.f, 0.f, 0.f, 0.f, 0.f};

    const int* xb = x + b * SS;

    for (int cs = 0; cs < 224; cs += 32) {   // 7 chunks of 32 (pads 200 -> 224)
        int  s    = cs + lane;
        bool live = (s < SS);
        int  idx  = live ? xb[live ? s : 0] : 0;
        // idx guarded; dead lanes read row 0 (exists) with weight 0
        if (!live) idx = 0;

        const float4* pr = (const float4*)(g_proj + (size_t)idx * 8);
        float4 pa = pr[0];
        float4 pb = pr[1];
        float g[5];
        g[0] = live ? __expf(fast_tanh(pa.x)) : 0.0f;
        g[1] = live ? __expf(fast_tanh(pa.y)) : 0.0f;
        g[2] = live ? __expf(fast_tanh(pa.z)) : 0.0f;
        g[3] = live ? __expf(fast_tanh(pa.w)) : 0.0f;
        g[4] = live ? __expf(fast_tanh(pb.x)) : 0.0f;
#pragma unroll
        for (int k = 0; k < 5; k++) lsum[k] += g[k];

#pragma unroll
        for (int i = 0; i < 8; i++) {
            int src  = i * 4 + grp;
            int ridx = __shfl_sync(0xffffffffu, idx, src);
            float h[5];
#pragma unroll
            for (int k = 0; k < 5; k++)
                h[k] = __shfl_sync(0xffffffffu, g[k], src);

            const float4* er = (const float4*)(emb + (size_t)ridx * DD + sub * 8);
            float4 e0 = er[0];
            float4 e1 = er[1];
#pragma unroll
            for (int k = 0; k < 5; k++) {
                acc[k][0] = fmaf(h[k], e0.x, acc[k][0]);
                acc[k][1] = fmaf(h[k], e0.y, acc[k][1]);
                acc[k][2] = fmaf(h[k], e0.z, acc[k][2]);
                acc[k][3] = fmaf(h[k], e0.w, acc[k][3]);
                acc[k][4] = fmaf(h[k], e1.x, acc[k][4]);
                acc[k][5] = fmaf(h[k], e1.y, acc[k][5]);
                acc[k][6] = fmaf(h[k], e1.z, acc[k][6]);
                acc[k][7] = fmaf(h[k], e1.w, acc[k][7]);
            }
        }
    }

    // Reduce acc across the 4 row-groups (lanes l, l^8, l^16, l^24)
#pragma unroll
    for (int k = 0; k < 5; k++)
#pragma unroll
        for (int j = 0; j < 8; j++) {
            acc[k][j] += __shfl_xor_sync(0xffffffffu, acc[k][j], 8);
            acc[k][j] += __shfl_xor_sync(0xffffffffu, acc[k][j], 16);
        }
    // Reduce lsum across the whole warp
#pragma unroll
    for (int k = 0; k < 5; k++) {
#pragma unroll
        for (int o = 16; o > 0; o >>= 1)
            lsum[k] += __shfl_xor_sync(0xffffffffu, lsum[k], o);
    }
    // Normalize: user_rep = acc / lsum
#pragma unroll
    for (int k = 0; k < 5; k++) {
        float inv = 1.0f / lsum[k];
#pragma unroll
        for (int j = 0; j < 8; j++) acc[k][j] *= inv;
    }

    // 18 head dot products: out_j = user_rep[attr] . W_attr[row]
    const float* Wp[5] = {W0, W1, W2, W3, W4};
    const int AL[5] = {2, 4, 4, 2, 6};
    float outv[18];
    int jg = 0;
#pragma unroll
    for (int i = 0; i < 5; i++) {
#pragma unroll
        for (int jj = 0; jj < AL[i]; jj++) {
            const float4* wr = (const float4*)(Wp[i] + jj * 64 + sub * 8);
            float4 w0 = wr[0];
            float4 w1 = wr[1];
            float p = acc[i][0] * w0.x + acc[i][1] * w0.y +
                      acc[i][2] * w0.z + acc[i][3] * w0.w +
                      acc[i][4] * w1.x + acc[i][5] * w1.y +
                      acc[i][6] * w1.z + acc[i][7] * w1.w;
            p += __shfl_xor_sync(0xffffffffu, p, 1);
            p += __shfl_xor_sync(0xffffffffu, p, 2);
            p += __shfl_xor_sync(0xffffffffu, p, 4);
            outv[jg++] = p;
        }
    }

    // Per-group softmax + cross-entropy loss (computed uniformly on all lanes)
    const float* yb = y + b * 18;
    float loss = 0.0f;
    float logits[18];
    int base = 0;
#pragma unroll
    for (int i = 0; i < 5; i++) {
        const int L = AL[i];
        float m = outv[base];
#pragma unroll
        for (int jj = 1; jj < L; jj++) m = fmaxf(m, outv[base + jj]);
        float ssum = 0.0f, dy = 0.0f;
#pragma unroll
        for (int jj = 0; jj < L; jj++) {
            float e = __expf(outv[base + jj] - m);
            logits[base + jj] = e;
            ssum += e;
            dy = fmaf(yb[base + jj], outv[base + jj], dy);
        }
        float inv = 1.0f / ssum;
#pragma unroll
        for (int jj = 0; jj < L; jj++) logits[base + jj] *= inv;
        loss += m + __logf(ssum) - dy;
        base += L;
    }

    if (lane == 0) {
#pragma unroll
        for (int j = 0; j < 18; j++) out[b * 18 + j] = logits[j];
        g_loss[b] = loss;
    }
}

// ---------------------------------------------------------------------------
// Kernel 3: deterministic loss reduction
// ---------------------------------------------------------------------------
__global__ void loss_reduce(float* __restrict__ out_loss) {
    __shared__ float s[256];
    float v = 0.0f;
    for (int i = threadIdx.x; i < BB; i += 256) v += g_loss[i];
    s[threadIdx.x] = v;
    __syncthreads();
    for (int o = 128; o > 0; o >>= 1) {
        if (threadIdx.x < o) s[threadIdx.x] += s[threadIdx.x + o];
        __syncthreads();
    }
    if (threadIdx.x == 0) *out_loss = s[0] * (1.0f / (float)BB);
}

// ---------------------------------------------------------------------------
extern "C" void kernel_launch(void* const* d_in, const int* in_sizes, int n_in,
                              void* d_out, int out_size) {
    const int*   x   = (const int*)  d_in[0];
    const float* y   = (const float*)d_in[1];
    const float* emb = (const float*)d_in[2];
    const float* aw  = (const float*)d_in[3];
    const float* ab  = (const float*)d_in[4];
    const float* W0  = (const float*)d_in[5];
    const float* W1  = (const float*)d_in[6];
    const float* W2  = (const float*)d_in[7];
    const float* W3  = (const float*)d_in[8];
    const float* W4  = (const float*)d_in[9];
    float* out = (float*)d_out;

    proj_kernel<<<(VV + 255) / 256, 256>>>(emb, aw, ab);
    main_kernel<<<BB / 4, 128>>>(x, y, emb, W0, W1, W2, W3, W4, out);
    loss_reduce<<<1, 256>>>(out + (out_size - 1));
}